// round 2
// baseline (speedup 1.0000x reference)
#include <cuda_runtime.h>
#include <math.h>

#define NN 100000
#define NE 600000
#define CC 128
#define NL 3
#define NS 10

// Scratch (allocation-free rule: __device__ globals), 16B-aligned for float4.
__device__ __align__(16) float g_m  [NN * CC];
__device__ __align__(16) float g_agg[NN * CC];
__device__ __align__(16) float g_gi [NN * 3 * CC];
__device__ __align__(16) float g_gh [NN * 3 * CC];
__device__ int g_src[NE];
__device__ int g_dst[NE];
__device__ int g_is64;   // 1 if edge_index buffer is int64-layout, else 0

// ---------------------------------------------------------------------------
// Edge-index dtype sniffing: reference declares int64, but JAX without x64
// emits int32. Inspect raw words: int64 little-endian layout has the high
// word of every element == 0 (indices in [0, 100000)).
// ---------------------------------------------------------------------------
__global__ void detect_k(const int* __restrict__ raw)
{
    int is64 = 1;
    for (int k = 0; k < 1024; k++) {
        int lo = raw[2 * k], hi = raw[2 * k + 1];
        if (hi != 0 || lo < 0 || lo >= NN) { is64 = 0; break; }
    }
    g_is64 = is64;
}

__global__ void convert_k(const int* __restrict__ raw)
{
    int e = blockIdx.x * blockDim.x + threadIdx.x;
    if (e >= NE) return;
    int s, d;
    if (g_is64) {
        s = raw[2 * e];                // low word of ei[0][e]
        d = raw[2 * (NE + e)];         // low word of ei[1][e]
    } else {
        s = raw[e];
        d = raw[NE + e];
    }
    // clamp defensively (avoid OOB even if detection is somehow fooled)
    s = min(max(s, 0), NN - 1);
    d = min(max(d, 0), NN - 1);
    g_src[e] = s;
    g_dst[e] = d;
}

// ---------------------------------------------------------------------------
// SGEMM: OUT[n,j] = sum_k IN[n,k] * W(j,k) (+ bias[j])
//   WT=true : W is [Cout,128] row-major, W(j,k) = W[j*128+k]   (w_ih/w_hh)
//   WT=false: W is [128,Cout] row-major, W(j,k) = W[k*Cout+j]  (per-step w)
// Tiles: 128(n) x 128(j) x 128(k, full), 256 threads, 8x8 per thread.
// ---------------------------------------------------------------------------
template<bool WT, bool HAS_BIAS>
__global__ __launch_bounds__(256, 1)
void gemm_k(const float* __restrict__ IN, const float* __restrict__ W,
            const float* __restrict__ bias, float* __restrict__ OUT,
            int N, int Cout)
{
    extern __shared__ float sm[];
    float* As = sm;                 // [128][128]  As[n*128+k]
    float* Bs = sm + 128 * 128;     // [128][128]  Bs[k*128+j]

    const int tid = threadIdx.x;
    const int n0 = blockIdx.x * 128;
    const int j0 = blockIdx.y * 128;

    // ---- load A tile ----
    #pragma unroll
    for (int i = tid; i < 128 * 32; i += 256) {
        int row = i >> 5;
        int kc  = (i & 31) << 2;
        float4 v = make_float4(0.f, 0.f, 0.f, 0.f);
        int gr = n0 + row;
        if (gr < N) v = *(const float4*)(IN + (size_t)gr * CC + kc);
        *(float4*)(As + row * 128 + kc) = v;
    }

    // ---- load B tile ----
    if (WT) {
        #pragma unroll
        for (int i = tid; i < 128 * 32; i += 256) {
            int j  = i & 127;
            int kc = (i >> 7) << 2;
            float4 v = *(const float4*)(W + (size_t)(j0 + j) * 128 + kc);
            Bs[(kc + 0) * 128 + j] = v.x;
            Bs[(kc + 1) * 128 + j] = v.y;
            Bs[(kc + 2) * 128 + j] = v.z;
            Bs[(kc + 3) * 128 + j] = v.w;
        }
    } else {
        #pragma unroll
        for (int i = tid; i < 128 * 32; i += 256) {
            int k  = i >> 5;
            int jc = (i & 31) << 2;
            float4 v = *(const float4*)(W + (size_t)k * Cout + j0 + jc);
            *(float4*)(Bs + k * 128 + jc) = v;
        }
    }
    __syncthreads();

    const int tx = tid & 15, ty = tid >> 4;
    const int nt = ty * 8, jt = tx * 8;

    float acc[8][8];
    #pragma unroll
    for (int i = 0; i < 8; i++)
        #pragma unroll
        for (int j = 0; j < 8; j++) acc[i][j] = 0.f;

    #pragma unroll 4
    for (int k = 0; k < 128; k++) {
        float a[8], b[8];
        #pragma unroll
        for (int i = 0; i < 8; i++) a[i] = As[(nt + i) * 128 + k];
        float4 b0 = *(const float4*)(Bs + k * 128 + jt);
        float4 b1 = *(const float4*)(Bs + k * 128 + jt + 4);
        b[0] = b0.x; b[1] = b0.y; b[2] = b0.z; b[3] = b0.w;
        b[4] = b1.x; b[5] = b1.y; b[6] = b1.z; b[7] = b1.w;
        #pragma unroll
        for (int i = 0; i < 8; i++)
            #pragma unroll
            for (int j = 0; j < 8; j++)
                acc[i][j] = fmaf(a[i], b[j], acc[i][j]);
    }

    float bv[8];
    if (HAS_BIAS) {
        #pragma unroll
        for (int j = 0; j < 8; j++) bv[j] = bias[j0 + jt + j];
    }

    #pragma unroll
    for (int i = 0; i < 8; i++) {
        int gr = n0 + nt + i;
        if (gr >= N) continue;
        float4 o0, o1;
        if (HAS_BIAS) {
            o0 = make_float4(acc[i][0] + bv[0], acc[i][1] + bv[1],
                             acc[i][2] + bv[2], acc[i][3] + bv[3]);
            o1 = make_float4(acc[i][4] + bv[4], acc[i][5] + bv[5],
                             acc[i][6] + bv[6], acc[i][7] + bv[7]);
        } else {
            o0 = make_float4(acc[i][0], acc[i][1], acc[i][2], acc[i][3]);
            o1 = make_float4(acc[i][4], acc[i][5], acc[i][6], acc[i][7]);
        }
        float* op = OUT + (size_t)gr * Cout + j0 + jt;
        *(float4*)(op)     = o0;
        *(float4*)(op + 4) = o1;
    }
}

// ---------------------------------------------------------------------------
// Edge scatter: agg[dst] += m[src], float4 atomics (sm_90+).
// 32 threads/edge (one per 16B chunk), coalesced gather & atomic.
// ---------------------------------------------------------------------------
__global__ void scatter_k(const float* __restrict__ m, float* __restrict__ agg)
{
    long long t = (long long)blockIdx.x * blockDim.x + threadIdx.x;
    int e = (int)(t >> 5);
    if (e >= NE) return;
    int c = ((int)t & 31) << 2;
    int s = g_src[e];
    int d = g_dst[e];
    float4 v = *(const float4*)(m + (size_t)s * CC + c);
    atomicAdd((float4*)(agg + (size_t)d * CC + c), v);
}

// ---------------------------------------------------------------------------
// GRU gate: h = (1-z)*tanh(i_n + r*h_n) + z*h ; optional ReLU (end of layer)
// ---------------------------------------------------------------------------
__global__ void gate_k(const float* __restrict__ gi, const float* __restrict__ gh,
                       float* __restrict__ h, int relu)
{
    int t = blockIdx.x * blockDim.x + threadIdx.x;
    if (t >= NN * CC) return;
    int n = t >> 7;
    int j = t & 127;
    const float* gin = gi + (size_t)n * 384;
    const float* ghn = gh + (size_t)n * 384;
    float i_r = gin[j], i_z = gin[128 + j], i_n = gin[256 + j];
    float h_r = ghn[j], h_z = ghn[128 + j], h_n = ghn[256 + j];
    float hv = h[t];
    float r = 1.f / (1.f + __expf(-(i_r + h_r)));
    float z = 1.f / (1.f + __expf(-(i_z + h_z)));
    float nn = tanhf(i_n + r * h_n);
    float o = (1.f - z) * nn + z * hv;
    if (relu) o = fmaxf(o, 0.f);
    h[t] = o;
}

// ---------------------------------------------------------------------------
extern "C" void kernel_launch(void* const* d_in, const int* in_sizes, int n_in,
                              void* d_out, int out_size)
{
    const float* x       = (const float*)d_in[0];
    const int*   ei_raw  = (const int*)d_in[1];   // int32 or int64 words; sniffed
    const float* weights = (const float*)d_in[2];
    const float* w_ih    = (const float*)d_in[3];
    const float* w_hh    = (const float*)d_in[4];
    const float* b_ih    = (const float*)d_in[5];
    const float* b_hh    = (const float*)d_in[6];
    float* h = (float*)d_out;

    void *pm, *pagg, *pgi, *pgh;
    cudaGetSymbolAddress(&pm,   g_m);
    cudaGetSymbolAddress(&pagg, g_agg);
    cudaGetSymbolAddress(&pgi,  g_gi);
    cudaGetSymbolAddress(&pgh,  g_gh);

    const int SMEM = 2 * 128 * 128 * (int)sizeof(float);  // 128 KB
    cudaFuncSetAttribute(gemm_k<false, false>,
                         cudaFuncAttributeMaxDynamicSharedMemorySize, SMEM);
    cudaFuncSetAttribute(gemm_k<true, true>,
                         cudaFuncAttributeMaxDynamicSharedMemorySize, SMEM);

    // Edge index normalization (dtype sniff + convert to int32)
    detect_k<<<1, 1>>>(ei_raw);
    convert_k<<<(NE + 255) / 256, 256>>>(ei_raw);

    // h <- x
    cudaMemcpyAsync(h, x, sizeof(float) * (size_t)NN * CC,
                    cudaMemcpyDeviceToDevice);

    const int NB = (NN + 127) / 128;  // 782

    for (int l = 0; l < NL; l++) {
        const float* wi = w_ih + (size_t)l * 3 * CC * CC;
        const float* wh = w_hh + (size_t)l * 3 * CC * CC;
        const float* bi = b_ih + (size_t)l * 3 * CC;
        const float* bh = b_hh + (size_t)l * 3 * CC;
        for (int s = 0; s < NS; s++) {
            const float* w = weights + ((size_t)l * NS + s) * CC * CC;

            // m = h @ w
            gemm_k<false, false><<<dim3(NB, 1), 256, SMEM>>>(
                h, w, nullptr, (float*)pm, NN, CC);

            // agg = segment_sum(m[src], dst)
            cudaMemsetAsync(pagg, 0, sizeof(float) * (size_t)NN * CC);
            scatter_k<<<(int)(((long long)NE * 32 + 255) / 256), 256>>>(
                (const float*)pm, (float*)pagg);

            // gi = agg @ wi^T + bi ; gh = h @ wh^T + bh
            gemm_k<true, true><<<dim3(NB, 3), 256, SMEM>>>(
                (const float*)pagg, wi, bi, (float*)pgi, NN, 3 * CC);
            gemm_k<true, true><<<dim3(NB, 3), 256, SMEM>>>(
                h, wh, bh, (float*)pgh, NN, 3 * CC);

            // GRU update (in place on h); ReLU after last step of layers 0,1
            int relu = (s == NS - 1 && l < NL - 1) ? 1 : 0;
            gate_k<<<(NN * CC + 255) / 256, 256>>>(
                (const float*)pgi, (const float*)pgh, h, relu);
        }
    }
}

// round 7
// speedup vs baseline: 1.0328x; 1.0328x over previous
#include <cuda_runtime.h>
#include <math.h>
#include <cstdint>

#define NN 100000
#define NE 600000
#define CC 128
#define NL 3
#define NS 10

// Scratch (allocation-free rule: __device__ globals), 16B-aligned.
__device__ __align__(16) float g_m  [NN * CC];
__device__ __align__(16) float g_agg[NN * CC];
__device__ __align__(16) float g_gi [NN * 3 * CC];
__device__ __align__(16) float g_gh [NN * 3 * CC];
__device__ int g_src[NE];
__device__ int g_dst[NE];
__device__ int g_is64;

// ============================================================================
// Edge-index normalization (int64-vs-int32 sniffing)
// ============================================================================
__global__ void detect_k(const int* __restrict__ raw) {
    int is64 = 1;
    for (int k = 0; k < 1024; k++) {
        int lo = raw[2 * k], hi = raw[2 * k + 1];
        if (hi != 0 || lo < 0 || lo >= NN) { is64 = 0; break; }
    }
    g_is64 = is64;
}
__global__ void convert_k(const int* __restrict__ raw) {
    int e = blockIdx.x * blockDim.x + threadIdx.x;
    if (e >= NE) return;
    int s, d;
    if (g_is64) { s = raw[2 * e]; d = raw[2 * (NE + e)]; }
    else        { s = raw[e];     d = raw[NE + e]; }
    g_src[e] = min(max(s, 0), NN - 1);
    g_dst[e] = min(max(d, 0), NN - 1);
}

// ============================================================================
// Packed-fp32 SGEMM via fma.rn.f32x2 — exact IEEE fp32 FMA, 2 lanes/op.
// Smem layouts IDENTICAL to the proven R2 kernel (row-major As, Bs, stride
// 128, float4/scalar accesses). Pairing done purely in registers:
//   acc pairs along j; B pair = (w0,w1) of existing float4 load,
//   A operand = register splat (a,a).
// OUT[n,j] = sum_k IN[n,k] * W(j,k) (+ bias[j])
//   WT=true : W [Cout,128] row-major, W(j,k)=W[j*128+k]
//   WT=false: W [128,Cout] row-major, W(j,k)=W[k*Cout+j]
// CTA: 128n x 128j x 128k, 256 threads, 8x8 micro-tile per thread.
// ============================================================================
#define SMEM_TOT (2 * 128 * 128 * 4)   // 128 KB

typedef unsigned long long u64;

__device__ __forceinline__ u64 packf2(float x, float y) {
    u64 r;
    asm("mov.b64 %0, {%1, %2};" : "=l"(r) : "f"(x), "f"(y));
    return r;
}
__device__ __forceinline__ void unpackf2(u64 p, float& x, float& y) {
    asm("mov.b64 {%0, %1}, %2;" : "=f"(x), "=f"(y) : "l"(p));
}
#define FMA2(c, a, b) \
    asm("fma.rn.f32x2 %0, %1, %2, %0;" : "+l"(c) : "l"(a), "l"(b))

template<bool WT, bool HAS_BIAS>
__global__ __launch_bounds__(256, 1)
void gemm2_k(const float* __restrict__ IN, const float* __restrict__ W,
             const float* __restrict__ bias, float* __restrict__ OUT,
             int Nrows, int Cout)
{
    extern __shared__ float sm[];
    float* As = sm;                 // [128][128]  As[row*128+k]
    float* Bs = sm + 128 * 128;     // [128][128]  Bs[k*128+j]

    const int tid = threadIdx.x;
    const int n0 = blockIdx.x * 128;
    const int j0 = blockIdx.y * 128;

    // ---- load A tile (coalesced, conflict-free) ----
    #pragma unroll
    for (int i = tid; i < 128 * 32; i += 256) {
        int row = i >> 5;
        int kc  = (i & 31) << 2;
        float4 v = make_float4(0.f, 0.f, 0.f, 0.f);
        int gr = n0 + row;
        if (gr < Nrows) v = *(const float4*)(IN + (size_t)gr * CC + kc);
        *(float4*)(As + row * 128 + kc) = v;
    }

    // ---- load B tile ----
    if (WT) {
        #pragma unroll
        for (int i = tid; i < 128 * 32; i += 256) {
            int j  = i & 127;
            int kc = (i >> 7) << 2;
            float4 v = *(const float4*)(W + (size_t)(j0 + j) * 128 + kc);
            Bs[(kc + 0) * 128 + j] = v.x;
            Bs[(kc + 1) * 128 + j] = v.y;
            Bs[(kc + 2) * 128 + j] = v.z;
            Bs[(kc + 3) * 128 + j] = v.w;
        }
    } else {
        #pragma unroll
        for (int i = tid; i < 128 * 32; i += 256) {
            int k  = i >> 5;
            int jc = (i & 31) << 2;
            float4 v = *(const float4*)(W + (size_t)k * Cout + j0 + jc);
            *(float4*)(Bs + k * 128 + jc) = v;
        }
    }
    __syncthreads();

    const int tx = tid & 15, ty = tid >> 4;
    const int nt = ty * 8, jt = tx * 8;

    // acc[i][jp]: row nt+i, column pair (jt+2jp, jt+2jp+1)
    u64 acc[8][4];
    #pragma unroll
    for (int i = 0; i < 8; i++)
        #pragma unroll
        for (int jp = 0; jp < 4; jp++) acc[i][jp] = 0ull;

    #pragma unroll 4
    for (int k = 0; k < 128; k++) {
        float4 b0 = *(const float4*)(Bs + k * 128 + jt);
        float4 b1 = *(const float4*)(Bs + k * 128 + jt + 4);
        u64 bp[4];
        bp[0] = packf2(b0.x, b0.y);
        bp[1] = packf2(b0.z, b0.w);
        bp[2] = packf2(b1.x, b1.y);
        bp[3] = packf2(b1.z, b1.w);
        u64 ad[8];
        #pragma unroll
        for (int i = 0; i < 8; i++) {
            float a = As[(nt + i) * 128 + k];
            ad[i] = packf2(a, a);
        }
        #pragma unroll
        for (int i = 0; i < 8; i++)
            #pragma unroll
            for (int jp = 0; jp < 4; jp++)
                FMA2(acc[i][jp], ad[i], bp[jp]);
    }

    // ---- epilogue: unpack, add bias, store float4 rows ----
    float bv[8];
    if (HAS_BIAS) {
        #pragma unroll
        for (int j = 0; j < 8; j++) bv[j] = bias[j0 + jt + j];
    }
    #pragma unroll
    for (int i = 0; i < 8; i++) {
        int gr = n0 + nt + i;
        if (gr >= Nrows) continue;
        float o[8];
        #pragma unroll
        for (int jp = 0; jp < 4; jp++)
            unpackf2(acc[i][jp], o[2 * jp], o[2 * jp + 1]);
        if (HAS_BIAS) {
            #pragma unroll
            for (int j = 0; j < 8; j++) o[j] += bv[j];
        }
        float* op = OUT + (size_t)gr * Cout + j0 + jt;
        *(float4*)(op)     = make_float4(o[0], o[1], o[2], o[3]);
        *(float4*)(op + 4) = make_float4(o[4], o[5], o[6], o[7]);
    }
}

// ============================================================================
// Edge scatter: agg[dst] += m[src], float4 atomics; 32 threads/edge
// ============================================================================
__global__ void scatter_k(const float* __restrict__ m, float* __restrict__ agg)
{
    long long t = (long long)blockIdx.x * blockDim.x + threadIdx.x;
    int e = (int)(t >> 5);
    if (e >= NE) return;
    int c = ((int)t & 31) << 2;
    int s = g_src[e];
    int d = g_dst[e];
    float4 v = *(const float4*)(m + (size_t)s * CC + c);
    atomicAdd((float4*)(agg + (size_t)d * CC + c), v);
}

// ============================================================================
// GRU gate: h = (1-z)*tanh(i_n + r*h_n) + z*h ; optional ReLU
// ============================================================================
__global__ void gate_k(const float* __restrict__ gi, const float* __restrict__ gh,
                       float* __restrict__ h, int relu)
{
    int t = blockIdx.x * blockDim.x + threadIdx.x;
    if (t >= NN * CC) return;
    int n = t >> 7;
    int j = t & 127;
    const float* gin = gi + (size_t)n * 384;
    const float* ghn = gh + (size_t)n * 384;
    float i_r = gin[j], i_z = gin[128 + j], i_n = gin[256 + j];
    float h_r = ghn[j], h_z = ghn[128 + j], h_n = ghn[256 + j];
    float hv = h[t];
    float r = 1.f / (1.f + __expf(-(i_r + h_r)));
    float z = 1.f / (1.f + __expf(-(i_z + h_z)));
    float nn = tanhf(i_n + r * h_n);
    float o = (1.f - z) * nn + z * hv;
    if (relu) o = fmaxf(o, 0.f);
    h[t] = o;
}

// ============================================================================
extern "C" void kernel_launch(void* const* d_in, const int* in_sizes, int n_in,
                              void* d_out, int out_size)
{
    const float* x       = (const float*)d_in[0];
    const int*   ei_raw  = (const int*)d_in[1];
    const float* weights = (const float*)d_in[2];
    const float* w_ih    = (const float*)d_in[3];
    const float* w_hh    = (const float*)d_in[4];
    const float* b_ih    = (const float*)d_in[5];
    const float* b_hh    = (const float*)d_in[6];
    float* h = (float*)d_out;

    void *pm, *pagg, *pgi, *pgh;
    cudaGetSymbolAddress(&pm,   g_m);
    cudaGetSymbolAddress(&pagg, g_agg);
    cudaGetSymbolAddress(&pgi,  g_gi);
    cudaGetSymbolAddress(&pgh,  g_gh);

    cudaFuncSetAttribute(gemm2_k<false, false>,
                         cudaFuncAttributeMaxDynamicSharedMemorySize, SMEM_TOT);
    cudaFuncSetAttribute(gemm2_k<true, true>,
                         cudaFuncAttributeMaxDynamicSharedMemorySize, SMEM_TOT);

    detect_k<<<1, 1>>>(ei_raw);
    convert_k<<<(NE + 255) / 256, 256>>>(ei_raw);

    cudaMemcpyAsync(h, x, sizeof(float) * (size_t)NN * CC,
                    cudaMemcpyDeviceToDevice);

    const int NB = (NN + 127) / 128;  // 782

    for (int l = 0; l < NL; l++) {
        const float* wi = w_ih + (size_t)l * 3 * CC * CC;
        const float* wh = w_hh + (size_t)l * 3 * CC * CC;
        const float* bi = b_ih + (size_t)l * 3 * CC;
        const float* bh = b_hh + (size_t)l * 3 * CC;
        for (int s = 0; s < NS; s++) {
            const float* w = weights + ((size_t)l * NS + s) * CC * CC;

            // m = h @ w
            gemm2_k<false, false><<<dim3(NB, 1), 256, SMEM_TOT>>>(
                h, w, nullptr, (float*)pm, NN, CC);

            // agg = segment_sum(m[src], dst)
            cudaMemsetAsync(pagg, 0, sizeof(float) * (size_t)NN * CC);
            scatter_k<<<(int)(((long long)NE * 32 + 255) / 256), 256>>>(
                (const float*)pm, (float*)pagg);

            // gi = agg @ wi^T + bi ; gh = h @ wh^T + bh
            gemm2_k<true, true><<<dim3(NB, 3), 256, SMEM_TOT>>>(
                (const float*)pagg, wi, bi, (float*)pgi, NN, 3 * CC);
            gemm2_k<true, true><<<dim3(NB, 3), 256, SMEM_TOT>>>(
                h, wh, bh, (float*)pgh, NN, 3 * CC);

            int relu = (s == NS - 1 && l < NL - 1) ? 1 : 0;
            gate_k<<<(NN * CC + 255) / 256, 256>>>(
                (const float*)pgi, (const float*)pgh, h, relu);
        }
    }
}